// round 2
// baseline (speedup 1.0000x reference)
#include <cuda_runtime.h>

// ---------------------------------------------------------------------------
// SSIM fusion loss:  1 - (SSIM(f,s1) + SSIM(f,s2)) / 2
// Separable 11-tap Gaussian blur (sigma=1.5), zero padding, fp32.
// One fused tile kernel (blur x2 passes + ssim map + block partial sum),
// then a tiny finalize kernel.
// ---------------------------------------------------------------------------

#define IMH 512
#define IMW 512
#define NPLANES 48              // B*C = 16*3
#define TW 32
#define TH 32
#define EXT 42                  // TH + 10
#define RSTR 43                 // raw tile row stride (odd -> conflict free)
#define HSTR 36                 // intermediate row stride (16B aligned cols)
#define NTHREADS 256
#define GX 16                   // IMW/TW
#define GY 16                   // IMH/TH
#define NBLOCKS (GX*GY*NPLANES) // 12288
#define NTOT 12582912.0         // 16*3*512*512

// Raw region is 3*EXT*RSTR = 5418 floats; pad to 5420 so the intermediate
// ("hint") region starts on a 16-byte boundary for float4 stores.
#define RAW_FLOATS   5420
#define SMEM_FLOATS (RAW_FLOATS + 8*EXT*HSTR)
#define SMEM_BYTES  (SMEM_FLOATS * 4)

__device__ float g_partial[NBLOCKS];

__global__ __launch_bounds__(NTHREADS)
void ssim_tile_kernel(const float* __restrict__ F,
                      const float* __restrict__ S1,
                      const float* __restrict__ S2)
{
    extern __shared__ float smem[];
    float* raw  = smem;                 // [3][EXT*RSTR]
    float* hint = smem + RAW_FLOATS;    // [8][EXT*HSTR], 16B-aligned

    const int tid = threadIdx.x;

    // --- Gaussian weights (normalized), computed in registers --------------
    float wgt[11];
    {
        float s = 0.f;
        #pragma unroll
        for (int j = 0; j < 11; ++j) {
            float d = (float)(j - 5);
            wgt[j] = expf(-d * d * (1.0f / 4.5f));
            s += wgt[j];
        }
        float inv = 1.0f / s;
        #pragma unroll
        for (int j = 0; j < 11; ++j) wgt[j] *= inv;
    }

    const int bx = blockIdx.x, by = blockIdx.y, bz = blockIdx.z;
    const int plane = bz * (IMH * IMW);
    const int x0 = bx * TW - 5;
    const int y0 = by * TH - 5;

    // --- Load extended (42x42) tile of f, s1, s2 with zero padding ---------
    for (int idx = tid; idx < EXT * EXT; idx += NTHREADS) {
        int r = idx / EXT;
        int c = idx - r * EXT;
        int gy = y0 + r;
        int gx = x0 + c;
        bool ok = (gy >= 0) && (gy < IMH) && (gx >= 0) && (gx < IMW);
        int off = plane + gy * IMW + gx;
        float f = ok ? __ldg(F  + off) : 0.f;
        float a = ok ? __ldg(S1 + off) : 0.f;
        float b = ok ? __ldg(S2 + off) : 0.f;
        raw[0 * EXT * RSTR + r * RSTR + c] = f;
        raw[1 * EXT * RSTR + r * RSTR + c] = a;
        raw[2 * EXT * RSTR + r * RSTR + c] = b;
    }
    __syncthreads();

    // --- Horizontal pass: 42 rows x 8 groups of 4 output columns ----------
    // Sliding window: each task covers cols c0..c0+3, reads cols c0..c0+14.
    for (int task = tid; task < EXT * 8; task += NTHREADS) {
        int r  = task >> 3;
        int g  = task & 7;
        int c0 = g * 4;

        float acc[8][4];
        #pragma unroll
        for (int k = 0; k < 8; ++k)
            #pragma unroll
            for (int o = 0; o < 4; ++o) acc[k][o] = 0.f;

        const float* r0p = &raw[0 * EXT * RSTR + r * RSTR + c0];
        const float* r1p = &raw[1 * EXT * RSTR + r * RSTR + c0];
        const float* r2p = &raw[2 * EXT * RSTR + r * RSTR + c0];

        #pragma unroll
        for (int cc = 0; cc < 15; ++cc) {
            float f = r0p[cc], a = r1p[cc], b = r2p[cc];
            float v0 = f,     v1 = a,     v2 = b;
            float v3 = f * f, v4 = a * a, v5 = b * b;
            float v6 = f * a, v7 = f * b;
            #pragma unroll
            for (int o = 0; o < 4; ++o) {
                int j = cc - o;
                if (j >= 0 && j < 11) {
                    float w = wgt[j];
                    acc[0][o] += w * v0;  acc[1][o] += w * v1;
                    acc[2][o] += w * v2;  acc[3][o] += w * v3;
                    acc[4][o] += w * v4;  acc[5][o] += w * v5;
                    acc[6][o] += w * v6;  acc[7][o] += w * v7;
                }
            }
        }
        #pragma unroll
        for (int k = 0; k < 8; ++k) {
            float4 st = make_float4(acc[k][0], acc[k][1], acc[k][2], acc[k][3]);
            *reinterpret_cast<float4*>(&hint[k * EXT * HSTR + r * HSTR + c0]) = st;
        }
    }
    __syncthreads();

    // --- Vertical pass + SSIM: each thread = 1 column x 4 output rows ------
    const int col = tid & 31;
    const int rg  = tid >> 5;      // 0..7
    const int r0v = rg * 4;

    float acc[8][4];
    #pragma unroll
    for (int k = 0; k < 8; ++k)
        #pragma unroll
        for (int o = 0; o < 4; ++o) acc[k][o] = 0.f;

    #pragma unroll
    for (int jj = 0; jj < 14; ++jj) {
        float v[8];
        #pragma unroll
        for (int k = 0; k < 8; ++k)
            v[k] = hint[k * EXT * HSTR + (r0v + jj) * HSTR + col];
        #pragma unroll
        for (int o = 0; o < 4; ++o) {
            int j = jj - o;
            if (j >= 0 && j < 11) {
                float w = wgt[j];
                #pragma unroll
                for (int k = 0; k < 8; ++k) acc[k][o] += w * v[k];
            }
        }
    }

    const float C1 = 1e-4f;   // 0.01^2
    const float C2 = 9e-4f;   // 0.03^2
    float lsum = 0.f;
    #pragma unroll
    for (int o = 0; o < 4; ++o) {
        float muF = acc[0][o], mu1 = acc[1][o], mu2 = acc[2][o];
        float eFF = acc[3][o], e11 = acc[4][o], e22 = acc[5][o];
        float eF1 = acc[6][o], eF2 = acc[7][o];

        float mFF = muF * muF, m11 = mu1 * mu1, m22 = mu2 * mu2;
        float pF1 = muF * mu1, pF2 = muF * mu2;

        float sF  = eFF - mFF;
        float s11 = e11 - m11;
        float s22 = e22 - m22;
        float c1v = eF1 - pF1;
        float c2v = eF2 - pF2;

        float num1 = (2.f * pF1 + C1) * (2.f * c1v + C2);
        float den1 = (mFF + m11 + C1) * (sF + s11 + C2);
        float num2 = (2.f * pF2 + C1) * (2.f * c2v + C2);
        float den2 = (mFF + m22 + C1) * (sF + s22 + C2);

        // s1 + s2 with a single reciprocal (MUFU budget!)
        lsum += __fdividef(num1 * den2 + num2 * den1, den1 * den2);
    }

    // --- Block reduction ---------------------------------------------------
    #pragma unroll
    for (int off = 16; off > 0; off >>= 1)
        lsum += __shfl_xor_sync(0xffffffffu, lsum, off);

    __shared__ float warpsum[8];
    if ((tid & 31) == 0) warpsum[tid >> 5] = lsum;
    __syncthreads();
    if (tid == 0) {
        float s = 0.f;
        #pragma unroll
        for (int i = 0; i < 8; ++i) s += warpsum[i];
        int bid = (bz * GY + by) * GX + bx;
        g_partial[bid] = s;
    }
}

__global__ __launch_bounds__(256)
void ssim_finalize_kernel(float* __restrict__ out)
{
    __shared__ double sh[256];
    double s = 0.0;
    for (int i = threadIdx.x; i < NBLOCKS; i += 256)
        s += (double)g_partial[i];
    sh[threadIdx.x] = s;
    __syncthreads();
    for (int k = 128; k > 0; k >>= 1) {
        if (threadIdx.x < k) sh[threadIdx.x] += sh[threadIdx.x + k];
        __syncthreads();
    }
    if (threadIdx.x == 0)
        out[0] = (float)(1.0 - sh[0] / (2.0 * NTOT));
}

extern "C" void kernel_launch(void* const* d_in, const int* in_sizes, int n_in,
                              void* d_out, int out_size)
{
    const float* F  = (const float*)d_in[0];
    const float* S1 = (const float*)d_in[1];
    const float* S2 = (const float*)d_in[2];

    static bool attr_set = false;
    if (!attr_set) {
        cudaFuncSetAttribute(ssim_tile_kernel,
                             cudaFuncAttributeMaxDynamicSharedMemorySize,
                             SMEM_BYTES);
        attr_set = true;
    }

    dim3 grid(GX, GY, NPLANES);
    ssim_tile_kernel<<<grid, NTHREADS, SMEM_BYTES>>>(F, S1, S2);
    ssim_finalize_kernel<<<1, 256>>>((float*)d_out);
}